// round 15
// baseline (speedup 1.0000x reference)
#include <cuda_runtime.h>
#include <cuda_fp16.h>
#include <cstdint>

#define NN 100000
#define EE 640000
#define EP 740000            /* EE + NN self loops */
#define CC 128
#define NEG_SLOPE 0.2f
#define SCAN_BLK 1024
#define NBLK ((NN + SCAN_BLK - 1) / SCAN_BLK)   /* 98 */

// ---------------- device scratch ---------------------------------------------
__device__ __align__(16) __half g_xl[(size_t)NN * CC];   // fp16: halves gather traffic
__device__ __align__(16) __half g_xr[(size_t)NN * CC];
__device__ __align__(16) float  g_h [(size_t)NN * CC];
__device__ __align__(16) __half g_Wh[6 * CC * CC];  // weights hi (fp16)
__device__ __align__(16) __half g_Wl[6 * CC * CC];  // weights lo (fp16)
__device__ int   g_deg[NN];
__device__ int   g_cur[NN];
__device__ int   g_off[NN];
__device__ int   g_bsum[NBLK];
__device__ int   g_csr[EP];

// ---------------- weight pre-split (fp32 -> fp16 hi/lo) -----------------------
__global__ void wsplit_kernel(const float* __restrict__ W0, const float* __restrict__ W1,
                              const float* __restrict__ W2, const float* __restrict__ W3,
                              const float* __restrict__ W4, const float* __restrict__ W5)
{
    const float* Ws[6] = {W0, W1, W2, W3, W4, W5};
    int i = blockIdx.x * blockDim.x + threadIdx.x;
    if (i >= 6 * CC * CC) return;
    float v = Ws[i >> 14][i & 16383];
    __half h = __float2half_rn(v);
    __half l = __float2half_rn(v - __half2float(h));
    g_Wh[i] = h;
    g_Wl[i] = l;
}

// ---------------- CSR build ---------------------------------------------------
__global__ void hist_kernel(const int* __restrict__ ei) {
    int e = blockIdx.x * blockDim.x + threadIdx.x;
    if (e >= EP) return;
    int d = (e < EE) ? ei[EE + e] : (e - EE);
    atomicAdd(&g_deg[d], 1);
}

__global__ void scan1_kernel() {
    __shared__ int sh[SCAN_BLK];
    int i = blockIdx.x * SCAN_BLK + threadIdx.x;
    int v = (i < NN) ? g_deg[i] : 0;
    sh[threadIdx.x] = v;
    __syncthreads();
    for (int o = 1; o < SCAN_BLK; o <<= 1) {
        int t = (threadIdx.x >= o) ? sh[threadIdx.x - o] : 0;
        __syncthreads();
        sh[threadIdx.x] += t;
        __syncthreads();
    }
    if (i < NN) g_off[i] = sh[threadIdx.x] - v;
    if (threadIdx.x == SCAN_BLK - 1) g_bsum[blockIdx.x] = sh[threadIdx.x];
}

__global__ void scan2_kernel() {
    __shared__ int sh[128];
    int b = threadIdx.x;
    int v = (b < NBLK) ? g_bsum[b] : 0;
    sh[b] = v;
    __syncthreads();
    for (int o = 1; o < 128; o <<= 1) {
        int t = (b >= o) ? sh[b - o] : 0;
        __syncthreads();
        sh[b] += t;
        __syncthreads();
    }
    if (b < NBLK) g_bsum[b] = sh[b] - v;
}

__global__ void scan3_kernel() {
    int i = blockIdx.x * blockDim.x + threadIdx.x;
    if (i < NN) g_off[i] += g_bsum[i / SCAN_BLK];
}

__global__ void scatter_kernel(const int* __restrict__ ei) {
    int e = blockIdx.x * blockDim.x + threadIdx.x;
    if (e >= EP) return;
    int s, d;
    if (e < EE) { s = ei[e]; d = ei[EE + e]; }
    else        { s = d = e - EE; }
    int pos = g_off[d] + atomicAdd(&g_cur[d], 1);
    g_csr[pos] = s;
}

// ================= HMMA (mma.sync) 3-output GEMM ==============================
// fp16 2-term split (validated: R12 2.79e-4 == predicted; R13 3.14e-4).
// D = Ah*Wh + Ah*Wl. 512 thr / 16 warps (4x4 of 32x32 tiles), cp.async
// double-buffered W. Outputs 0,1 (xl,xr scratch) fp16; output 2 fp32.
#define AS_STRIDE 136                    /* fp16 units; LDSM rows 272B apart -> conflict-free */
#define TILE_B (128 * AS_STRIDE * 2)     /* 34816 bytes */
#define SM_AH  0
#define SM_BB  (TILE_B)                  /* B buffers: buf*(2*TILE_B) + {0:hi, TILE_B:lo} */
#define SM_TOTAL (5 * TILE_B)            /* 174080 = 170 KB */

__device__ __forceinline__ void mma16816(float* c, const uint32_t* a,
                                         const uint32_t* b) {
    asm volatile(
        "mma.sync.aligned.m16n8k16.row.col.f32.f16.f16.f32 "
        "{%0,%1,%2,%3}, {%4,%5,%6,%7}, {%8,%9}, {%0,%1,%2,%3};"
        : "+f"(c[0]), "+f"(c[1]), "+f"(c[2]), "+f"(c[3])
        : "r"(a[0]), "r"(a[1]), "r"(a[2]), "r"(a[3]), "r"(b[0]), "r"(b[1]));
}

__device__ __forceinline__ void ldsm_x4(uint32_t* r, uint32_t addr) {
    asm volatile("ldmatrix.sync.aligned.m8n8.x4.shared.b16 {%0,%1,%2,%3}, [%4];"
                 : "=r"(r[0]), "=r"(r[1]), "=r"(r[2]), "=r"(r[3]) : "r"(addr));
}

__device__ __forceinline__ void cp_async16(uint32_t dst, const void* src) {
    asm volatile("cp.async.cg.shared.global [%0], [%1], 16;"
                 :: "r"(dst), "l"(src));
}
#define CP_COMMIT() asm volatile("cp.async.commit_group;" ::: "memory")
#define CP_WAIT1()  asm volatile("cp.async.wait_group 1;" ::: "memory")
#define CP_WAIT0()  asm volatile("cp.async.wait_group 0;" ::: "memory")

// prefetch one pre-split W tile (hi+lo) into a B buffer via cp.async
__device__ __forceinline__ void prefetch_w(const __half* srch, const __half* srcl,
                                           uint32_t dsth, uint32_t dstl, int tid) {
#pragma unroll
    for (int t = 0; t < 4; t++) {
        int idx = tid + t * 512;         // 2048 x 16B per tile
        int row = idx >> 4;
        int k8  = (idx & 15) << 3;
        uint32_t off = (uint32_t)(row * AS_STRIDE + k8) * 2;
        cp_async16(dsth + off, srch + row * CC + k8);
        cp_async16(dstl + off, srcl + row * CC + k8);
    }
}

__global__ __launch_bounds__(512, 1) void gemm3_tc_kernel(
    const float* __restrict__ x,
    const __half* __restrict__ Wh, const __half* __restrict__ Wl,
    int mat0,
    const float* __restrict__ b0, __half* __restrict__ o0,
    const float* __restrict__ b1, __half* __restrict__ o1,
    const float* __restrict__ b2, float* __restrict__ o2,
    int relu_in)
{
    extern __shared__ char sm[];
    const int tid  = threadIdx.x;
    const int wid  = tid >> 5;
    const int lane = tid & 31;
    const int g    = lane >> 2;          // 0..7
    const int tg   = lane & 3;           // 0..3
    const int row0 = blockIdx.x * 128;
    const int nrows = (NN - row0 < 128) ? (NN - row0) : 128;
    const int wm0 = (wid >> 2) * 32;     // warp tile m origin (0/32/64/96)
    const int wn0 = (wid & 3) * 32;      // warp tile n origin (0/32/64/96)

    const uint32_t smb = (uint32_t)__cvta_generic_to_shared(sm);

    // prefetch B(0) immediately (overlaps with A conversion below)
    prefetch_w(Wh + (size_t)mat0 * CC * CC, Wl + (size_t)mat0 * CC * CC,
               smb + SM_BB, smb + SM_BB + TILE_B, tid);
    CP_COMMIT();

    // A tile -> fp16 (rounded); 4096 float4 over 512 threads
#pragma unroll
    for (int t = 0; t < 8; t++) {
        int idx = tid + t * 512;
        int row = idx >> 5;
        int k4  = (idx & 31) << 2;
        float4 v = make_float4(0.f, 0.f, 0.f, 0.f);
        if (row < nrows)
            v = *(const float4*)(x + (size_t)(row0 + row) * CC + k4);
        if (relu_in) {
            v.x = fmaxf(v.x, 0.f); v.y = fmaxf(v.y, 0.f);
            v.z = fmaxf(v.z, 0.f); v.w = fmaxf(v.w, 0.f);
        }
        __half2 p0 = __floats2half2_rn(v.x, v.y);
        __half2 p1 = __floats2half2_rn(v.z, v.w);
        uint32_t off = (uint32_t)(row * AS_STRIDE + k4) * 2;
        *(__half2*)(sm + SM_AH + off)     = p0;
        *(__half2*)(sm + SM_AH + off + 4) = p1;
    }

    // ldmatrix per-lane base addresses
    const uint32_t a_lane_off =
        (uint32_t)(((wm0 + (lane & 15)) * AS_STRIDE + ((lane >> 4) << 3)) * 2);
    const uint32_t ah_base = smb + SM_AH + a_lane_off;
    const int b_row = (lane & 7) + ((lane & 16) ? 8 : 0);
    const uint32_t b_lane_off =
        (uint32_t)(((wn0 + b_row) * AS_STRIDE + ((lane & 8) ? 8 : 0)) * 2);

    for (int j = 0; j < 3; j++) {
        if (j + 1 < 3) {                 // prefetch B(j+1) into alternate buffer
            uint32_t bb = smb + SM_BB + (uint32_t)(((j + 1) & 1) * 2 * TILE_B);
            prefetch_w(Wh + (size_t)(mat0 + j + 1) * CC * CC,
                       Wl + (size_t)(mat0 + j + 1) * CC * CC,
                       bb, bb + TILE_B, tid);
            CP_COMMIT();
            CP_WAIT1();                  // B(j) complete (one newer group pending)
        } else {
            CP_WAIT0();
        }
        __syncthreads();                 // B(j) visible; A visible (j==0)

        const uint32_t bbase = smb + SM_BB + (uint32_t)((j & 1) * 2 * TILE_B);
        const uint32_t bhi_base = bbase + b_lane_off;
        const uint32_t blo_base = bbase + TILE_B + b_lane_off;

        float acc[2][4][4];
#pragma unroll
        for (int ma = 0; ma < 2; ma++)
#pragma unroll
            for (int na = 0; na < 4; na++)
#pragma unroll
                for (int q = 0; q < 4; q++) acc[ma][na][q] = 0.f;

#pragma unroll
        for (int ks = 0; ks < 8; ks++) {
            const uint32_t kso = (uint32_t)(ks * 16 * 2);
            uint32_t bh[4][2], bl[4][2], af[2][4];
#pragma unroll
            for (int nap = 0; nap < 2; nap++) {
                uint32_t r[4];
                ldsm_x4(r, bhi_base + (uint32_t)(nap * 16 * AS_STRIDE * 2) + kso);
                bh[nap * 2][0] = r[0]; bh[nap * 2][1] = r[1];
                bh[nap * 2 + 1][0] = r[2]; bh[nap * 2 + 1][1] = r[3];
                ldsm_x4(r, blo_base + (uint32_t)(nap * 16 * AS_STRIDE * 2) + kso);
                bl[nap * 2][0] = r[0]; bl[nap * 2][1] = r[1];
                bl[nap * 2 + 1][0] = r[2]; bl[nap * 2 + 1][1] = r[3];
            }
#pragma unroll
            for (int ma = 0; ma < 2; ma++)
                ldsm_x4(af[ma], ah_base + (uint32_t)(ma * 16 * AS_STRIDE * 2) + kso);
#pragma unroll
            for (int ma = 0; ma < 2; ma++)
#pragma unroll
                for (int na = 0; na < 4; na++)
                    mma16816(acc[ma][na], af[ma], bh[na]);
#pragma unroll
            for (int ma = 0; ma < 2; ma++)
#pragma unroll
                for (int na = 0; na < 4; na++)
                    mma16816(acc[ma][na], af[ma], bl[na]);
        }

        // epilogue: bias + gmem stores. j=0,1 -> fp16 (xl/xr scratch); j=2 -> fp32.
        if (j < 2) {
            const float* bias = (j == 0) ? b0 : b1;
            __half* o = (j == 0) ? o0 : o1;
#pragma unroll
            for (int na = 0; na < 4; na++) {
                int col = wn0 + na * 8 + tg * 2;
                float2 bb2 = *(const float2*)(bias + col);
#pragma unroll
                for (int ma = 0; ma < 2; ma++) {
                    int ra = row0 + wm0 + ma * 16 + g;
                    if (ra < NN) {
                        *(__half2*)(o + (size_t)ra * CC + col) =
                            __floats2half2_rn(acc[ma][na][0] + bb2.x,
                                              acc[ma][na][1] + bb2.y);
                    }
                    int rb = ra + 8;
                    if (rb < NN) {
                        *(__half2*)(o + (size_t)rb * CC + col) =
                            __floats2half2_rn(acc[ma][na][2] + bb2.x,
                                              acc[ma][na][3] + bb2.y);
                    }
                }
            }
        } else {
#pragma unroll
            for (int na = 0; na < 4; na++) {
                int col = wn0 + na * 8 + tg * 2;
                float2 bb2 = *(const float2*)(b2 + col);
#pragma unroll
                for (int ma = 0; ma < 2; ma++) {
                    int ra = row0 + wm0 + ma * 16 + g;
                    if (ra < NN) {
                        float2 v = make_float2(acc[ma][na][0] + bb2.x,
                                               acc[ma][na][1] + bb2.y);
                        *(float2*)(o2 + (size_t)ra * CC + col) = v;
                    }
                    int rb = ra + 8;
                    if (rb < NN) {
                        float2 v = make_float2(acc[ma][na][2] + bb2.x,
                                               acc[ma][na][3] + bb2.y);
                        *(float2*)(o2 + (size_t)rb * CC + col) = v;
                    }
                }
            }
        }
        __syncthreads();                 // buf (j&1) consumed before j+2 prefetch
    }
}

// ---------------- fused attention + aggregation (warp per dst, no atomics) ---
// xl/xr fp16 storage (256B row gathers), fp32 arithmetic. 4-edge unroll:
// MLP=4 on L2 gathers (also hides PTW), 4 interleaved shuffle chains.
__device__ __forceinline__ float4 load_half_row4(const __half* base, size_t row,
                                                 int lane) {
    uint2 u = *(const uint2*)(base + row * CC + lane * 4);
    __half2 h0 = *(__half2*)&u.x;
    __half2 h1 = *(__half2*)&u.y;
    float2 f0 = __half22float2(h0);
    float2 f1 = __half22float2(h1);
    return make_float4(f0.x, f0.y, f1.x, f1.y);
}

__device__ __forceinline__ float leaky_dot(float4 a, float4 r, float4 t) {
    float4 m;
    m.x = a.x + r.x; m.x = m.x > 0.f ? m.x : NEG_SLOPE * m.x;
    m.y = a.y + r.y; m.y = m.y > 0.f ? m.y : NEG_SLOPE * m.y;
    m.z = a.z + r.z; m.z = m.z > 0.f ? m.z : NEG_SLOPE * m.z;
    m.w = a.w + r.w; m.w = m.w > 0.f ? m.w : NEG_SLOPE * m.w;
    float p = m.x * t.x;
    p = fmaf(m.y, t.y, p);
    p = fmaf(m.z, t.z, p);
    p = fmaf(m.w, t.w, p);
    return p;
}

__global__ __launch_bounds__(256) void aggr_kernel(
    const __half* __restrict__ xl, const __half* __restrict__ xr,
    const float* __restrict__ att, float* __restrict__ res_out)
{
    int gw   = (int)((blockIdx.x * 256u + threadIdx.x) >> 5);
    int lane = threadIdx.x & 31;
    if (gw >= NN) return;
    const int d = gw;

    float4 t = *(const float4*)(att + lane * 4);
    float4 r = load_half_row4(xr, (size_t)d, lane);

    const int start = g_off[d];
    const int deg   = g_deg[d];          // >= 1 (self loop)

    float denom = 0.f;
    float4 acc = make_float4(0.f, 0.f, 0.f, 0.f);

    int jj = 0;
    for (; jj + 3 < deg; jj += 4) {
        int s0 = g_csr[start + jj];
        int s1 = g_csr[start + jj + 1];
        int s2 = g_csr[start + jj + 2];
        int s3 = g_csr[start + jj + 3];
        float4 a0 = load_half_row4(xl, (size_t)s0, lane);
        float4 a1 = load_half_row4(xl, (size_t)s1, lane);
        float4 a2 = load_half_row4(xl, (size_t)s2, lane);
        float4 a3 = load_half_row4(xl, (size_t)s3, lane);
        float p0 = leaky_dot(a0, r, t);
        float p1 = leaky_dot(a1, r, t);
        float p2 = leaky_dot(a2, r, t);
        float p3 = leaky_dot(a3, r, t);
#pragma unroll
        for (int off = 16; off > 0; off >>= 1) {
            p0 += __shfl_xor_sync(0xffffffffu, p0, off);
            p1 += __shfl_xor_sync(0xffffffffu, p1, off);
            p2 += __shfl_xor_sync(0xffffffffu, p2, off);
            p3 += __shfl_xor_sync(0xffffffffu, p3, off);
        }
        float ev0 = expf(p0);
        float ev1 = expf(p1);
        float ev2 = expf(p2);
        float ev3 = expf(p3);
        denom += (ev0 + ev1) + (ev2 + ev3);
        acc.x = fmaf(ev0, a0.x, fmaf(ev1, a1.x, fmaf(ev2, a2.x, fmaf(ev3, a3.x, acc.x))));
        acc.y = fmaf(ev0, a0.y, fmaf(ev1, a1.y, fmaf(ev2, a2.y, fmaf(ev3, a3.y, acc.y))));
        acc.z = fmaf(ev0, a0.z, fmaf(ev1, a1.z, fmaf(ev2, a2.z, fmaf(ev3, a3.z, acc.z))));
        acc.w = fmaf(ev0, a0.w, fmaf(ev1, a1.w, fmaf(ev2, a2.w, fmaf(ev3, a3.w, acc.w))));
    }
    for (; jj + 1 < deg; jj += 2) {
        int s0 = g_csr[start + jj];
        int s1 = g_csr[start + jj + 1];
        float4 a0 = load_half_row4(xl, (size_t)s0, lane);
        float4 a1 = load_half_row4(xl, (size_t)s1, lane);
        float p0 = leaky_dot(a0, r, t);
        float p1 = leaky_dot(a1, r, t);
#pragma unroll
        for (int off = 16; off > 0; off >>= 1) {
            p0 += __shfl_xor_sync(0xffffffffu, p0, off);
            p1 += __shfl_xor_sync(0xffffffffu, p1, off);
        }
        float ev0 = expf(p0);
        float ev1 = expf(p1);
        denom += ev0 + ev1;
        acc.x = fmaf(ev0, a0.x, fmaf(ev1, a1.x, acc.x));
        acc.y = fmaf(ev0, a0.y, fmaf(ev1, a1.y, acc.y));
        acc.z = fmaf(ev0, a0.z, fmaf(ev1, a1.z, acc.z));
        acc.w = fmaf(ev0, a0.w, fmaf(ev1, a1.w, acc.w));
    }
    if (jj < deg) {
        int s0 = g_csr[start + jj];
        float4 a0 = load_half_row4(xl, (size_t)s0, lane);
        float p0 = leaky_dot(a0, r, t);
#pragma unroll
        for (int off = 16; off > 0; off >>= 1)
            p0 += __shfl_xor_sync(0xffffffffu, p0, off);
        float ev0 = expf(p0);
        denom += ev0;
        acc.x = fmaf(ev0, a0.x, acc.x);
        acc.y = fmaf(ev0, a0.y, acc.y);
        acc.z = fmaf(ev0, a0.z, acc.z);
        acc.w = fmaf(ev0, a0.w, acc.w);
    }

    float inv = 1.f / denom;
    float* op = res_out + (size_t)d * CC + lane * 4;
    float4 rr = *(const float4*)op;
    float4 o = make_float4(fmaf(acc.x, inv, rr.x), fmaf(acc.y, inv, rr.y),
                           fmaf(acc.z, inv, rr.z), fmaf(acc.w, inv, rr.w));
    *(float4*)op = o;
}

// ---------------- launch ------------------------------------------------------
extern "C" void kernel_launch(void* const* d_in, const int* in_sizes, int n_in,
                              void* d_out, int out_size)
{
    const int*   ei    = (const int*)  d_in[0];
    const float* emb   = (const float*)d_in[1];
    const float* Wl1   = (const float*)d_in[2];
    const float* bl1   = (const float*)d_in[3];
    const float* Wr1   = (const float*)d_in[4];
    const float* br1   = (const float*)d_in[5];
    const float* att1  = (const float*)d_in[6];
    const float* Wres1 = (const float*)d_in[7];
    const float* bias1 = (const float*)d_in[8];
    const float* Wl2   = (const float*)d_in[9];
    const float* bl2   = (const float*)d_in[10];
    const float* Wr2   = (const float*)d_in[11];
    const float* br2   = (const float*)d_in[12];
    const float* att2  = (const float*)d_in[13];
    const float* Wres2 = (const float*)d_in[14];
    const float* bias2 = (const float*)d_in[15];
    float* out = (float*)d_out;

    __half *xl, *xr, *Wh, *Wl;
    float *h;
    int *deg, *cur;
    cudaGetSymbolAddress((void**)&xl,  g_xl);
    cudaGetSymbolAddress((void**)&xr,  g_xr);
    cudaGetSymbolAddress((void**)&h,   g_h);
    cudaGetSymbolAddress((void**)&Wh,  g_Wh);
    cudaGetSymbolAddress((void**)&Wl,  g_Wl);
    cudaGetSymbolAddress((void**)&deg, g_deg);
    cudaGetSymbolAddress((void**)&cur, g_cur);

    cudaFuncSetAttribute(gemm3_tc_kernel,
                         cudaFuncAttributeMaxDynamicSharedMemorySize, SM_TOTAL);

    const int edge_grid = (EP + 255) / 256;        // 2891
    const int gemm_grid = (NN + 127) / 128;        // 782
    const int aggr_grid = (NN * 32 + 255) / 256;   // 12500

    // Launch order chosen so ncu (-s 5 -c 1, memsets count) captures gemm3_tc.
    cudaMemsetAsync(deg, 0, NN * sizeof(int));                      // 0
    cudaMemsetAsync(cur, 0, NN * sizeof(int));                      // 1
    wsplit_kernel<<<(6 * CC * CC + 255) / 256, 256>>>(              // 2
        Wl1, Wr1, Wres1, Wl2, Wr2, Wres2);
    hist_kernel<<<edge_grid, 256>>>(ei);                            // 3
    scan1_kernel<<<NBLK, SCAN_BLK>>>();                             // 4
    gemm3_tc_kernel<<<gemm_grid, 512, SM_TOTAL>>>(                  // 5  <- profiled
        emb, Wh, Wl, 0, bl1, xl, br1, xr, bias1, h, 0);
    scan2_kernel<<<1, 128>>>();                                     // 6
    scan3_kernel<<<(NN + 255) / 256, 256>>>();                      // 7
    scatter_kernel<<<edge_grid, 256>>>(ei);                         // 8
    aggr_kernel<<<aggr_grid, 256>>>(xl, xr, att1, h);               // 9
    gemm3_tc_kernel<<<gemm_grid, 512, SM_TOTAL>>>(                  // 10
        h, Wh, Wl, 3, bl2, xl, br2, xr, bias2, out, 1);
    aggr_kernel<<<aggr_grid, 256>>>(xl, xr, att2, out);             // 11
}

// round 16
// speedup vs baseline: 1.0273x; 1.0273x over previous
#include <cuda_runtime.h>
#include <cuda_fp16.h>
#include <cstdint>

#define NN 100000
#define EE 640000
#define EP 740000            /* EE + NN self loops */
#define CC 128
#define NEG_SLOPE 0.2f
#define SCAN_BLK 1024
#define NBLK ((NN + SCAN_BLK - 1) / SCAN_BLK)   /* 98 */

// ---------------- device scratch ---------------------------------------------
__device__ __align__(16) __half g_xl[(size_t)NN * CC];   // fp16: halves gather traffic
__device__ __align__(16) __half g_xr[(size_t)NN * CC];
__device__ __align__(16) float  g_h [(size_t)NN * CC];
__device__ __align__(16) __half g_Wh[6 * CC * CC];  // weights hi (fp16)
__device__ __align__(16) __half g_Wl[6 * CC * CC];  // weights lo (fp16)
__device__ int   g_deg[NN];
__device__ int   g_cur[NN];
__device__ int   g_off[NN];
__device__ int   g_bsum[NBLK];
__device__ int   g_csr[EP];

// ---------------- weight pre-split (fp32 -> fp16 hi/lo) -----------------------
__global__ void wsplit_kernel(const float* __restrict__ W0, const float* __restrict__ W1,
                              const float* __restrict__ W2, const float* __restrict__ W3,
                              const float* __restrict__ W4, const float* __restrict__ W5)
{
    const float* Ws[6] = {W0, W1, W2, W3, W4, W5};
    int i = blockIdx.x * blockDim.x + threadIdx.x;
    if (i >= 6 * CC * CC) return;
    float v = Ws[i >> 14][i & 16383];
    __half h = __float2half_rn(v);
    __half l = __float2half_rn(v - __half2float(h));
    g_Wh[i] = h;
    g_Wl[i] = l;
}

// ---------------- CSR build ---------------------------------------------------
__global__ void hist_kernel(const int* __restrict__ ei) {
    int e = blockIdx.x * blockDim.x + threadIdx.x;
    if (e >= EP) return;
    int d = (e < EE) ? ei[EE + e] : (e - EE);
    atomicAdd(&g_deg[d], 1);
}

__global__ void scan1_kernel() {
    __shared__ int sh[SCAN_BLK];
    int i = blockIdx.x * SCAN_BLK + threadIdx.x;
    int v = (i < NN) ? g_deg[i] : 0;
    sh[threadIdx.x] = v;
    __syncthreads();
    for (int o = 1; o < SCAN_BLK; o <<= 1) {
        int t = (threadIdx.x >= o) ? sh[threadIdx.x - o] : 0;
        __syncthreads();
        sh[threadIdx.x] += t;
        __syncthreads();
    }
    if (i < NN) g_off[i] = sh[threadIdx.x] - v;
    if (threadIdx.x == SCAN_BLK - 1) g_bsum[blockIdx.x] = sh[threadIdx.x];
}

__global__ void scan2_kernel() {
    __shared__ int sh[128];
    int b = threadIdx.x;
    int v = (b < NBLK) ? g_bsum[b] : 0;
    sh[b] = v;
    __syncthreads();
    for (int o = 1; o < 128; o <<= 1) {
        int t = (b >= o) ? sh[b - o] : 0;
        __syncthreads();
        sh[b] += t;
        __syncthreads();
    }
    if (b < NBLK) g_bsum[b] = sh[b] - v;
}

__global__ void scan3_kernel() {
    int i = blockIdx.x * blockDim.x + threadIdx.x;
    if (i < NN) g_off[i] += g_bsum[i / SCAN_BLK];
}

__global__ void scatter_kernel(const int* __restrict__ ei) {
    int e = blockIdx.x * blockDim.x + threadIdx.x;
    if (e >= EP) return;
    int s, d;
    if (e < EE) { s = ei[e]; d = ei[EE + e]; }
    else        { s = d = e - EE; }
    int pos = g_off[d] + atomicAdd(&g_cur[d], 1);
    g_csr[pos] = s;
}

// ================= HMMA (mma.sync) 3-output GEMM ==============================
// fp16 2-term split (validated: R12 2.79e-4 == predicted; R13 3.14e-4).
// D = Ah*Wh + Ah*Wl. 512 thr / 16 warps (4x4 of 32x32 tiles), cp.async
// double-buffered W. Outputs 0,1 (xl,xr scratch) fp16; output 2 fp32.
#define AS_STRIDE 136                    /* fp16 units; LDSM rows 272B apart -> conflict-free */
#define TILE_B (128 * AS_STRIDE * 2)     /* 34816 bytes */
#define SM_AH  0
#define SM_BB  (TILE_B)                  /* B buffers: buf*(2*TILE_B) + {0:hi, TILE_B:lo} */
#define SM_TOTAL (5 * TILE_B)            /* 174080 = 170 KB */

__device__ __forceinline__ void mma16816(float* c, const uint32_t* a,
                                         const uint32_t* b) {
    asm volatile(
        "mma.sync.aligned.m16n8k16.row.col.f32.f16.f16.f32 "
        "{%0,%1,%2,%3}, {%4,%5,%6,%7}, {%8,%9}, {%0,%1,%2,%3};"
        : "+f"(c[0]), "+f"(c[1]), "+f"(c[2]), "+f"(c[3])
        : "r"(a[0]), "r"(a[1]), "r"(a[2]), "r"(a[3]), "r"(b[0]), "r"(b[1]));
}

__device__ __forceinline__ void ldsm_x4(uint32_t* r, uint32_t addr) {
    asm volatile("ldmatrix.sync.aligned.m8n8.x4.shared.b16 {%0,%1,%2,%3}, [%4];"
                 : "=r"(r[0]), "=r"(r[1]), "=r"(r[2]), "=r"(r[3]) : "r"(addr));
}

__device__ __forceinline__ void cp_async16(uint32_t dst, const void* src) {
    asm volatile("cp.async.cg.shared.global [%0], [%1], 16;"
                 :: "r"(dst), "l"(src));
}
#define CP_COMMIT() asm volatile("cp.async.commit_group;" ::: "memory")
#define CP_WAIT1()  asm volatile("cp.async.wait_group 1;" ::: "memory")
#define CP_WAIT0()  asm volatile("cp.async.wait_group 0;" ::: "memory")

// prefetch one pre-split W tile (hi+lo) into a B buffer via cp.async
__device__ __forceinline__ void prefetch_w(const __half* srch, const __half* srcl,
                                           uint32_t dsth, uint32_t dstl, int tid) {
#pragma unroll
    for (int t = 0; t < 4; t++) {
        int idx = tid + t * 512;         // 2048 x 16B per tile
        int row = idx >> 4;
        int k8  = (idx & 15) << 3;
        uint32_t off = (uint32_t)(row * AS_STRIDE + k8) * 2;
        cp_async16(dsth + off, srch + row * CC + k8);
        cp_async16(dstl + off, srcl + row * CC + k8);
    }
}

__global__ __launch_bounds__(512, 1) void gemm3_tc_kernel(
    const float* __restrict__ x,
    const __half* __restrict__ Wh, const __half* __restrict__ Wl,
    int mat0,
    const float* __restrict__ b0, __half* __restrict__ o0,
    const float* __restrict__ b1, __half* __restrict__ o1,
    const float* __restrict__ b2, float* __restrict__ o2,
    int relu_in)
{
    extern __shared__ char sm[];
    const int tid  = threadIdx.x;
    const int wid  = tid >> 5;
    const int lane = tid & 31;
    const int g    = lane >> 2;          // 0..7
    const int tg   = lane & 3;           // 0..3
    const int row0 = blockIdx.x * 128;
    const int nrows = (NN - row0 < 128) ? (NN - row0) : 128;
    const int wm0 = (wid >> 2) * 32;     // warp tile m origin (0/32/64/96)
    const int wn0 = (wid & 3) * 32;      // warp tile n origin (0/32/64/96)

    const uint32_t smb = (uint32_t)__cvta_generic_to_shared(sm);

    // prefetch B(0) immediately (overlaps with A conversion below)
    prefetch_w(Wh + (size_t)mat0 * CC * CC, Wl + (size_t)mat0 * CC * CC,
               smb + SM_BB, smb + SM_BB + TILE_B, tid);
    CP_COMMIT();

    // A tile -> fp16 (rounded); 4096 float4 over 512 threads
#pragma unroll
    for (int t = 0; t < 8; t++) {
        int idx = tid + t * 512;
        int row = idx >> 5;
        int k4  = (idx & 31) << 2;
        float4 v = make_float4(0.f, 0.f, 0.f, 0.f);
        if (row < nrows)
            v = *(const float4*)(x + (size_t)(row0 + row) * CC + k4);
        if (relu_in) {
            v.x = fmaxf(v.x, 0.f); v.y = fmaxf(v.y, 0.f);
            v.z = fmaxf(v.z, 0.f); v.w = fmaxf(v.w, 0.f);
        }
        __half2 p0 = __floats2half2_rn(v.x, v.y);
        __half2 p1 = __floats2half2_rn(v.z, v.w);
        uint32_t off = (uint32_t)(row * AS_STRIDE + k4) * 2;
        *(__half2*)(sm + SM_AH + off)     = p0;
        *(__half2*)(sm + SM_AH + off + 4) = p1;
    }

    // ldmatrix per-lane base addresses
    const uint32_t a_lane_off =
        (uint32_t)(((wm0 + (lane & 15)) * AS_STRIDE + ((lane >> 4) << 3)) * 2);
    const uint32_t ah_base = smb + SM_AH + a_lane_off;
    const int b_row = (lane & 7) + ((lane & 16) ? 8 : 0);
    const uint32_t b_lane_off =
        (uint32_t)(((wn0 + b_row) * AS_STRIDE + ((lane & 8) ? 8 : 0)) * 2);

    for (int j = 0; j < 3; j++) {
        if (j + 1 < 3) {                 // prefetch B(j+1) into alternate buffer
            uint32_t bb = smb + SM_BB + (uint32_t)(((j + 1) & 1) * 2 * TILE_B);
            prefetch_w(Wh + (size_t)(mat0 + j + 1) * CC * CC,
                       Wl + (size_t)(mat0 + j + 1) * CC * CC,
                       bb, bb + TILE_B, tid);
            CP_COMMIT();
            CP_WAIT1();                  // B(j) complete (one newer group pending)
        } else {
            CP_WAIT0();
        }
        __syncthreads();                 // B(j) visible; A visible (j==0)

        const uint32_t bbase = smb + SM_BB + (uint32_t)((j & 1) * 2 * TILE_B);
        const uint32_t bhi_base = bbase + b_lane_off;
        const uint32_t blo_base = bbase + TILE_B + b_lane_off;

        float acc[2][4][4];
#pragma unroll
        for (int ma = 0; ma < 2; ma++)
#pragma unroll
            for (int na = 0; na < 4; na++)
#pragma unroll
                for (int q = 0; q < 4; q++) acc[ma][na][q] = 0.f;

#pragma unroll
        for (int ks = 0; ks < 8; ks++) {
            const uint32_t kso = (uint32_t)(ks * 16 * 2);
            uint32_t bh[4][2], bl[4][2], af[2][4];
#pragma unroll
            for (int nap = 0; nap < 2; nap++) {
                uint32_t r[4];
                ldsm_x4(r, bhi_base + (uint32_t)(nap * 16 * AS_STRIDE * 2) + kso);
                bh[nap * 2][0] = r[0]; bh[nap * 2][1] = r[1];
                bh[nap * 2 + 1][0] = r[2]; bh[nap * 2 + 1][1] = r[3];
                ldsm_x4(r, blo_base + (uint32_t)(nap * 16 * AS_STRIDE * 2) + kso);
                bl[nap * 2][0] = r[0]; bl[nap * 2][1] = r[1];
                bl[nap * 2 + 1][0] = r[2]; bl[nap * 2 + 1][1] = r[3];
            }
#pragma unroll
            for (int ma = 0; ma < 2; ma++)
                ldsm_x4(af[ma], ah_base + (uint32_t)(ma * 16 * AS_STRIDE * 2) + kso);
#pragma unroll
            for (int ma = 0; ma < 2; ma++)
#pragma unroll
                for (int na = 0; na < 4; na++)
                    mma16816(acc[ma][na], af[ma], bh[na]);
#pragma unroll
            for (int ma = 0; ma < 2; ma++)
#pragma unroll
                for (int na = 0; na < 4; na++)
                    mma16816(acc[ma][na], af[ma], bl[na]);
        }

        // epilogue: bias + gmem stores. j=0,1 -> fp16 (xl/xr scratch); j=2 -> fp32.
        if (j < 2) {
            const float* bias = (j == 0) ? b0 : b1;
            __half* o = (j == 0) ? o0 : o1;
#pragma unroll
            for (int na = 0; na < 4; na++) {
                int col = wn0 + na * 8 + tg * 2;
                float2 bb2 = *(const float2*)(bias + col);
#pragma unroll
                for (int ma = 0; ma < 2; ma++) {
                    int ra = row0 + wm0 + ma * 16 + g;
                    if (ra < NN) {
                        *(__half2*)(o + (size_t)ra * CC + col) =
                            __floats2half2_rn(acc[ma][na][0] + bb2.x,
                                              acc[ma][na][1] + bb2.y);
                    }
                    int rb = ra + 8;
                    if (rb < NN) {
                        *(__half2*)(o + (size_t)rb * CC + col) =
                            __floats2half2_rn(acc[ma][na][2] + bb2.x,
                                              acc[ma][na][3] + bb2.y);
                    }
                }
            }
        } else {
#pragma unroll
            for (int na = 0; na < 4; na++) {
                int col = wn0 + na * 8 + tg * 2;
                float2 bb2 = *(const float2*)(b2 + col);
#pragma unroll
                for (int ma = 0; ma < 2; ma++) {
                    int ra = row0 + wm0 + ma * 16 + g;
                    if (ra < NN) {
                        float2 v = make_float2(acc[ma][na][0] + bb2.x,
                                               acc[ma][na][1] + bb2.y);
                        *(float2*)(o2 + (size_t)ra * CC + col) = v;
                    }
                    int rb = ra + 8;
                    if (rb < NN) {
                        float2 v = make_float2(acc[ma][na][2] + bb2.x,
                                               acc[ma][na][3] + bb2.y);
                        *(float2*)(o2 + (size_t)rb * CC + col) = v;
                    }
                }
            }
        }
        __syncthreads();                 // buf (j&1) consumed before j+2 prefetch
    }
}

// ---------------- fused attention + aggregation (warp per dst, no atomics) ---
// xl/xr fp16 (256B gathers via __ldcg: L2-only, no L1 thrash on a 25MB
// working set). 64-thread blocks: retire granularity = max of 2 warps (not 8)
// -> degree-imbalance tail becomes schedulable slack. 4-edge unroll retained.
__device__ __forceinline__ float4 load_half_row4(const __half* base, size_t row,
                                                 int lane) {
    uint2 u = __ldcg((const uint2*)(base + row * CC + lane * 4));
    __half2 h0 = *(__half2*)&u.x;
    __half2 h1 = *(__half2*)&u.y;
    float2 f0 = __half22float2(h0);
    float2 f1 = __half22float2(h1);
    return make_float4(f0.x, f0.y, f1.x, f1.y);
}

__device__ __forceinline__ float leaky_dot(float4 a, float4 r, float4 t) {
    float4 m;
    m.x = a.x + r.x; m.x = m.x > 0.f ? m.x : NEG_SLOPE * m.x;
    m.y = a.y + r.y; m.y = m.y > 0.f ? m.y : NEG_SLOPE * m.y;
    m.z = a.z + r.z; m.z = m.z > 0.f ? m.z : NEG_SLOPE * m.z;
    m.w = a.w + r.w; m.w = m.w > 0.f ? m.w : NEG_SLOPE * m.w;
    float p = m.x * t.x;
    p = fmaf(m.y, t.y, p);
    p = fmaf(m.z, t.z, p);
    p = fmaf(m.w, t.w, p);
    return p;
}

__global__ __launch_bounds__(64) void aggr_kernel(
    const __half* __restrict__ xl, const __half* __restrict__ xr,
    const float* __restrict__ att, float* __restrict__ res_out)
{
    int gw   = (int)((blockIdx.x * 64u + threadIdx.x) >> 5);
    int lane = threadIdx.x & 31;
    if (gw >= NN) return;
    const int d = gw;

    float4 t = *(const float4*)(att + lane * 4);
    float4 r = load_half_row4(xr, (size_t)d, lane);

    const int start = g_off[d];
    const int deg   = g_deg[d];          // >= 1 (self loop)

    float denom = 0.f;
    float4 acc = make_float4(0.f, 0.f, 0.f, 0.f);

    int jj = 0;
    for (; jj + 3 < deg; jj += 4) {
        int s0 = g_csr[start + jj];
        int s1 = g_csr[start + jj + 1];
        int s2 = g_csr[start + jj + 2];
        int s3 = g_csr[start + jj + 3];
        float4 a0 = load_half_row4(xl, (size_t)s0, lane);
        float4 a1 = load_half_row4(xl, (size_t)s1, lane);
        float4 a2 = load_half_row4(xl, (size_t)s2, lane);
        float4 a3 = load_half_row4(xl, (size_t)s3, lane);
        float p0 = leaky_dot(a0, r, t);
        float p1 = leaky_dot(a1, r, t);
        float p2 = leaky_dot(a2, r, t);
        float p3 = leaky_dot(a3, r, t);
#pragma unroll
        for (int off = 16; off > 0; off >>= 1) {
            p0 += __shfl_xor_sync(0xffffffffu, p0, off);
            p1 += __shfl_xor_sync(0xffffffffu, p1, off);
            p2 += __shfl_xor_sync(0xffffffffu, p2, off);
            p3 += __shfl_xor_sync(0xffffffffu, p3, off);
        }
        float ev0 = expf(p0);
        float ev1 = expf(p1);
        float ev2 = expf(p2);
        float ev3 = expf(p3);
        denom += (ev0 + ev1) + (ev2 + ev3);
        acc.x = fmaf(ev0, a0.x, fmaf(ev1, a1.x, fmaf(ev2, a2.x, fmaf(ev3, a3.x, acc.x))));
        acc.y = fmaf(ev0, a0.y, fmaf(ev1, a1.y, fmaf(ev2, a2.y, fmaf(ev3, a3.y, acc.y))));
        acc.z = fmaf(ev0, a0.z, fmaf(ev1, a1.z, fmaf(ev2, a2.z, fmaf(ev3, a3.z, acc.z))));
        acc.w = fmaf(ev0, a0.w, fmaf(ev1, a1.w, fmaf(ev2, a2.w, fmaf(ev3, a3.w, acc.w))));
    }
    for (; jj + 1 < deg; jj += 2) {
        int s0 = g_csr[start + jj];
        int s1 = g_csr[start + jj + 1];
        float4 a0 = load_half_row4(xl, (size_t)s0, lane);
        float4 a1 = load_half_row4(xl, (size_t)s1, lane);
        float p0 = leaky_dot(a0, r, t);
        float p1 = leaky_dot(a1, r, t);
#pragma unroll
        for (int off = 16; off > 0; off >>= 1) {
            p0 += __shfl_xor_sync(0xffffffffu, p0, off);
            p1 += __shfl_xor_sync(0xffffffffu, p1, off);
        }
        float ev0 = expf(p0);
        float ev1 = expf(p1);
        denom += ev0 + ev1;
        acc.x = fmaf(ev0, a0.x, fmaf(ev1, a1.x, acc.x));
        acc.y = fmaf(ev0, a0.y, fmaf(ev1, a1.y, acc.y));
        acc.z = fmaf(ev0, a0.z, fmaf(ev1, a1.z, acc.z));
        acc.w = fmaf(ev0, a0.w, fmaf(ev1, a1.w, acc.w));
    }
    if (jj < deg) {
        int s0 = g_csr[start + jj];
        float4 a0 = load_half_row4(xl, (size_t)s0, lane);
        float p0 = leaky_dot(a0, r, t);
#pragma unroll
        for (int off = 16; off > 0; off >>= 1)
            p0 += __shfl_xor_sync(0xffffffffu, p0, off);
        float ev0 = expf(p0);
        denom += ev0;
        acc.x = fmaf(ev0, a0.x, acc.x);
        acc.y = fmaf(ev0, a0.y, acc.y);
        acc.z = fmaf(ev0, a0.z, acc.z);
        acc.w = fmaf(ev0, a0.w, acc.w);
    }

    float inv = 1.f / denom;
    float* op = res_out + (size_t)d * CC + lane * 4;
    float4 rr = *(const float4*)op;
    float4 o = make_float4(fmaf(acc.x, inv, rr.x), fmaf(acc.y, inv, rr.y),
                           fmaf(acc.z, inv, rr.z), fmaf(acc.w, inv, rr.w));
    *(float4*)op = o;
}

// ---------------- launch ------------------------------------------------------
extern "C" void kernel_launch(void* const* d_in, const int* in_sizes, int n_in,
                              void* d_out, int out_size)
{
    const int*   ei    = (const int*)  d_in[0];
    const float* emb   = (const float*)d_in[1];
    const float* Wl1   = (const float*)d_in[2];
    const float* bl1   = (const float*)d_in[3];
    const float* Wr1   = (const float*)d_in[4];
    const float* br1   = (const float*)d_in[5];
    const float* att1  = (const float*)d_in[6];
    const float* Wres1 = (const float*)d_in[7];
    const float* bias1 = (const float*)d_in[8];
    const float* Wl2   = (const float*)d_in[9];
    const float* bl2   = (const float*)d_in[10];
    const float* Wr2   = (const float*)d_in[11];
    const float* br2   = (const float*)d_in[12];
    const float* att2  = (const float*)d_in[13];
    const float* Wres2 = (const float*)d_in[14];
    const float* bias2 = (const float*)d_in[15];
    float* out = (float*)d_out;

    __half *xl, *xr, *Wh, *Wl;
    float *h;
    int *deg, *cur;
    cudaGetSymbolAddress((void**)&xl,  g_xl);
    cudaGetSymbolAddress((void**)&xr,  g_xr);
    cudaGetSymbolAddress((void**)&h,   g_h);
    cudaGetSymbolAddress((void**)&Wh,  g_Wh);
    cudaGetSymbolAddress((void**)&Wl,  g_Wl);
    cudaGetSymbolAddress((void**)&deg, g_deg);
    cudaGetSymbolAddress((void**)&cur, g_cur);

    cudaFuncSetAttribute(gemm3_tc_kernel,
                         cudaFuncAttributeMaxDynamicSharedMemorySize, SM_TOTAL);

    const int edge_grid = (EP + 255) / 256;        // 2891
    const int gemm_grid = (NN + 127) / 128;        // 782
    const int aggr_grid = (NN * 32 + 63) / 64;     // 50000 blocks of 2 warps

    // Launch order chosen so ncu (-s 5 -c 1, memsets count) captures gemm3_tc.
    cudaMemsetAsync(deg, 0, NN * sizeof(int));                      // 0
    cudaMemsetAsync(cur, 0, NN * sizeof(int));                      // 1
    wsplit_kernel<<<(6 * CC * CC + 255) / 256, 256>>>(              // 2
        Wl1, Wr1, Wres1, Wl2, Wr2, Wres2);
    hist_kernel<<<edge_grid, 256>>>(ei);                            // 3
    scan1_kernel<<<NBLK, SCAN_BLK>>>();                             // 4
    gemm3_tc_kernel<<<gemm_grid, 512, SM_TOTAL>>>(                  // 5  <- profiled
        emb, Wh, Wl, 0, bl1, xl, br1, xr, bias1, h, 0);
    scan2_kernel<<<1, 128>>>();                                     // 6
    scan3_kernel<<<(NN + 255) / 256, 256>>>();                      // 7
    scatter_kernel<<<edge_grid, 256>>>(ei);                         // 8
    aggr_kernel<<<aggr_grid, 64>>>(xl, xr, att1, h);                // 9
    gemm3_tc_kernel<<<gemm_grid, 512, SM_TOTAL>>>(                  // 10
        h, Wh, Wl, 3, bl2, xl, br2, xr, bias2, out, 1);
    aggr_kernel<<<aggr_grid, 64>>>(xl, xr, att2, out);              // 11
}